// round 2
// baseline (speedup 1.0000x reference)
#include <cuda_runtime.h>
#include <cstdint>

// Conv2d direct: input (64,8,256,256) f32 NCHW, filter (8,8,3,3) OIHW,
// VALID, stride 1 -> out (64,8,254,254) f32.
//
// R2: column-pair f32x2 packing. Each thread computes 2 adjacent output
// columns x 4 rows x 8 M channels. The f32x2 FMA input operand is the pair of
// adjacent input pixels -> loaded directly with LDS.64 (s=0,2) or one pack
// (s=1). Weights are pre-DUPLICATED in SMEM as {w,w} float2 so the broadcast
// operand needs zero ALU. This removes the per-value broadcast packs that made
// alu% == fma% in R1.

#define CONV_N 64
#define CONV_C 8
#define CONV_H 256
#define CONV_W 256
#define CONV_M 8
#define CONV_P 254
#define CONV_Q 254

#define TILE_W 64      // output columns per block (32 threads x 2 cols)
#define TILE_H 32      // output rows per block (8 ty x 4 rows)
#define JPT 4          // rows per thread
#define CPB 4          // channels per smem pass

__global__ __launch_bounds__(256, 2)
void Im2Col_Conv2d_6854767804820_kernel(const float* __restrict__ in,
                                        const float* __restrict__ filt,
                                        float* __restrict__ out)
{
    __shared__ float  sIn[CPB][TILE_H + 2][TILE_W + 2];   // 4*34*66*4 = 35904 B
    __shared__ float2 sWd[CONV_C * 9][CONV_M];            // 72*8*8    =  4608 B

    const int tx  = threadIdx.x;            // 0..31  (column pair)
    const int ty  = threadIdx.y;            // 0..7   (row group)
    const int tid = ty * 32 + tx;

    const int col0 = blockIdx.x * TILE_W;   // 0,64,128,192
    const int row0 = blockIdx.y * TILE_H;   // 0..224
    const int n    = blockIdx.z;

    // ---- load filter, duplicated: sWd[rem][m] = {w, w}
    // global filt layout: [m][c][r][s] -> f[m*72 + rem], rem = (c*3+r)*3+s
    for (int i = tid; i < CONV_M * CONV_C * 9; i += 256) {
        int m   = i / 72;
        int rem = i % 72;
        float w = filt[m * 72 + rem];
        sWd[rem][m] = make_float2(w, w);
    }

    const float* inN = in + (size_t)n * CONV_C * CONV_H * CONV_W;

    // accumulators: 4 rows x 8 m, each a packed f32x2 over the column pair
    unsigned long long acc[JPT][CONV_M];
#pragma unroll
    for (int j = 0; j < JPT; j++)
#pragma unroll
        for (int m = 0; m < CONV_M; m++) acc[j][m] = 0ull;

    const int rbase = ty * JPT;     // first output row (tile-local)
    const int q2    = 2 * tx;       // first output col (tile-local)

    for (int cb = 0; cb < CONV_C / CPB; cb++) {
        __syncthreads();   // protect previous pass's tile

        // ---- stage CPB channels of the input halo tile: CPB * 34 * 66 floats
        for (int i = tid; i < CPB * (TILE_H + 2) * (TILE_W + 2); i += 256) {
            int col = i % (TILE_W + 2);
            int t   = i / (TILE_W + 2);
            int row = t % (TILE_H + 2);
            int cl  = t / (TILE_H + 2);
            int gr = row0 + row;
            int gc = col0 + col;
            float v = 0.0f;
            if (gr < CONV_H && gc < CONV_W)
                v = inN[((size_t)(cb * CPB + cl) * CONV_H + gr) * CONV_W + gc];
            sIn[cl][row][col] = v;
        }
        __syncthreads();

#pragma unroll
        for (int cl = 0; cl < CPB; cl++) {
            const int c = cb * CPB + cl;

#pragma unroll
            for (int r = 0; r < 3; r++) {
                // Load the 4 input rows this r needs: cols q2..q2+3.
                // xa = {x0,x1} (s=0), xb = {x2,x3} (s=2), xm = {x1,x2} (s=1).
                unsigned long long xa[JPT], xb[JPT], xm[JPT];
#pragma unroll
                for (int j = 0; j < JPT; j++) {
                    const float* p = &sIn[cl][rbase + r + j][q2];
                    float2 lo = *reinterpret_cast<const float2*>(p);      // LDS.64
                    float2 hi = *reinterpret_cast<const float2*>(p + 2);  // LDS.64
                    asm("mov.b64 %0, {%1, %2};" : "=l"(xa[j]) : "f"(lo.x), "f"(lo.y));
                    asm("mov.b64 %0, {%1, %2};" : "=l"(xm[j]) : "f"(lo.y), "f"(hi.x));
                    asm("mov.b64 %0, {%1, %2};" : "=l"(xb[j]) : "f"(hi.x), "f"(hi.y));
                }

#pragma unroll
                for (int s = 0; s < 3; s++) {
                    // broadcast weight pairs {w,w} for all 8 m (LDS.64 broadcast)
                    unsigned long long w2[CONV_M];
                    const unsigned long long* wrow =
                        reinterpret_cast<const unsigned long long*>(&sWd[(c * 3 + r) * 3 + s][0]);
#pragma unroll
                    for (int m = 0; m < CONV_M; m++) w2[m] = wrow[m];

#pragma unroll
                    for (int j = 0; j < JPT; j++) {
                        unsigned long long xv = (s == 0) ? xa[j] : (s == 1) ? xm[j] : xb[j];
#pragma unroll
                        for (int m = 0; m < CONV_M; m++) {
                            asm("fma.rn.f32x2 %0, %1, %2, %0;"
                                : "+l"(acc[j][m])
                                : "l"(xv), "l"(w2[m]));
                        }
                    }
                }
            }
        }
    }

    // ---- store: out[n][m][orow][ocol], column pair via STG.64
    const int ocol = col0 + q2;
    if (ocol < CONV_Q) {        // pair never straddles the boundary (Q even)
        float* outN = out + (size_t)n * CONV_M * CONV_P * CONV_Q;
#pragma unroll
        for (int j = 0; j < JPT; j++) {
            int orow = row0 + rbase + j;
            if (orow < CONV_P) {
#pragma unroll
                for (int m = 0; m < CONV_M; m++) {
                    *reinterpret_cast<unsigned long long*>(
                        &outN[((size_t)m * CONV_P + orow) * CONV_Q + ocol]) = acc[j][m];
                }
            }
        }
    }
}

extern "C" void kernel_launch(void* const* d_in, const int* in_sizes, int n_in,
                              void* d_out, int out_size)
{
    const float* input  = (const float*)d_in[0];   // (64,8,256,256)
    const float* filter = (const float*)d_in[1];   // (8,8,3,3)
    float* output = (float*)d_out;                 // (64,8,254,254)

    dim3 block(32, 8, 1);
    dim3 grid((CONV_Q + TILE_W - 1) / TILE_W,      // 4
              (CONV_P + TILE_H - 1) / TILE_H,      // 8
              CONV_N);                             // 64
    Im2Col_Conv2d_6854767804820_kernel<<<grid, block>>>(input, filter, output);
}